// round 16
// baseline (speedup 1.0000x reference)
#include <cuda_runtime.h>
#include <math.h>
#include <stdint.h>

#define BB 8
#define NN 4096
#define DIM 1024
#define GRID 148            // 1 CTA/SM (160 KB smem forces this anyway)
#define TOTAL_ROWS (BB * NN)
#define CHUNK 16            // rows per dynamic grab = one 64 KB TMA bulk copy
#define CHUNK_BYTES (CHUNK * DIM * 4)

// Dynamic smem: v (8192 f) + 2 x-buffers (16384 f each) = 163840 B
#define DSMEM_FLOATS (8192 + 2 * 16384)
#define DSMEM_BYTES (DSMEM_FLOATS * 4)

// Scratch (no allocation allowed). Zero at load; g_row reset at end of run.
__device__ float g_q0[BB * DIM];
__device__ float g_v[BB * DIM];
__device__ float g_scores[BB * NN];
__device__ unsigned int g_b1, g_b2, g_b3;  // monotonic barrier counters
__device__ unsigned int g_row;             // phase-3 ticket (reset at end)

__device__ __forceinline__ float warp_sum(float v) {
#pragma unroll
    for (int off = 16; off > 0; off >>= 1)
        v += __shfl_down_sync(0xFFFFFFFFu, v, off);
    return v;
}

__device__ __forceinline__ uint32_t smem_u32(const void* p) {
    uint32_t a;
    asm("{ .reg .u64 t; cvta.to.shared.u64 t, %1; cvt.u32.u64 %0, t; }"
        : "=r"(a) : "l"(p));
    return a;
}

// Monotonic grid barrier: atomic arrival, volatile-load poll.
__device__ __forceinline__ void grid_barrier(unsigned int* ctr) {
    __shared__ unsigned int s_tk;
    __threadfence();
    __syncthreads();
    if (threadIdx.x == 0) s_tk = atomicAdd(ctr, 1u);
    __syncthreads();
    unsigned int target = (s_tk / GRID + 1u) * GRID;
    if (threadIdx.x == 0) {
        volatile unsigned int* vc = (volatile unsigned int*)ctr;
        while (*vc < target) __nanosleep(32);
    }
    __syncthreads();
    __threadfence();
}

__device__ __forceinline__ void mbar_init(uint32_t mbar, uint32_t count) {
    asm volatile("mbarrier.init.shared.b64 [%0], %1;" :: "r"(mbar), "r"(count)
                 : "memory");
}
__device__ __forceinline__ void mbar_expect_tx(uint32_t mbar, uint32_t bytes) {
    asm volatile("mbarrier.arrive.expect_tx.shared.b64 _, [%0], %1;"
                 :: "r"(mbar), "r"(bytes) : "memory");
}
__device__ __forceinline__ void mbar_wait(uint32_t mbar, uint32_t parity) {
    asm volatile(
        "{\n\t.reg .pred P;\n\t"
        "WL_%=:\n\t"
        "mbarrier.try_wait.parity.acquire.cta.shared::cta.b64 P, [%0], %1, 0x989680;\n\t"
        "@P bra.uni WD_%=;\n\t"
        "bra.uni WL_%=;\n\t"
        "WD_%=:\n\t}"
        :: "r"(mbar), "r"(parity) : "memory");
}
__device__ __forceinline__ void tma_bulk_g2s(uint32_t dst_smem, const void* src,
                                             uint32_t bytes, uint32_t mbar) {
    asm volatile(
        "cp.async.bulk.shared::cta.global.mbarrier::complete_tx::bytes "
        "[%0], [%1], %2, [%3];"
        :: "r"(dst_smem), "l"(src), "r"(bytes), "r"(mbar) : "memory");
}

extern __shared__ float dyn[];  // [0,8192): v/stage; [8192,+32768): x buffers

__global__ void __launch_bounds__(512, 1)
k_fused(const float* __restrict__ x, const float* __restrict__ Wq,
        const float* __restrict__ bq, const float* __restrict__ Wk,
        float* __restrict__ out) {
    __shared__ float qs[BB][16];
    __shared__ float red[16];
    __shared__ float bcast;
    __shared__ unsigned int s_r0;
    __shared__ uint64_t mbar_store[2];

    int tid = threadIdx.x;
    int bx = blockIdx.x;
    int warp = tid >> 5, lane = tid & 31;
    const char* xb = (const char*)x;

    uint32_t mb0 = smem_u32(&mbar_store[0]);
    uint32_t mb1 = smem_u32(&mbar_store[1]);
    if (tid == 0) {
        mbar_init(mb0, 1);
        mbar_init(mb1, 1);
    }
    __syncthreads();  // mbarriers visible before any TMA

    // ========= Phase 1 (blocks 0..127): q0 = Wq@x0 + bq  (atomic halves) ==
    // Blocks 128..147: fire-and-forget L2 prefetch of early x rows.
    if (bx < 128) {
        float4* stage = (float4*)dyn;  // 2048 float4 = 32 KB
#pragma unroll
        for (int j = 0; j < 4; j++) {
            int idx = tid + 512 * j;
            int b = idx >> 8, d4 = idx & 255;
            stage[idx] = ((const float4*)x)[(size_t)b * (NN * DIM / 4) + d4];
        }
        __syncthreads();

        int gw = bx * 16 + warp;      // 0..2047
        int e = gw >> 1;
        int h = gw & 1;
        int base = h * 128;
        const float4* wrow4 = (const float4*)Wq + (size_t)e * 256 + base;

        float acc[BB];
#pragma unroll
        for (int b = 0; b < BB; b++) acc[b] = 0.0f;
#pragma unroll
        for (int j = 0; j < 4; j++) {
            int i = lane + 32 * j;
            float4 w4 = wrow4[i];
#pragma unroll
            for (int b = 0; b < BB; b++) {
                float4 x4 = stage[b * 256 + base + i];
                acc[b] += w4.x * x4.x + w4.y * x4.y + w4.z * x4.z + w4.w * x4.w;
            }
        }
#pragma unroll
        for (int b = 0; b < BB; b++) acc[b] = warp_sum(acc[b]);
        if (lane == 0) {
            float bias = (h == 0) ? bq[e] : 0.0f;
#pragma unroll
            for (int b = 0; b < BB; b++)
                atomicAdd(&g_q0[b * DIM + e], acc[b] + bias);
        }
    } else {
        // 20 blocks x 16 warps x 8 rows = 2560 rows (10 MB) into L2.
        int pb = bx - 128;
        int r0 = pb * 128 + warp * 8;
#pragma unroll
        for (int k = 0; k < 8; k++) {
            size_t off = ((size_t)(r0 + k) << 12) + ((size_t)lane << 7);
            asm volatile("prefetch.global.L2 [%0];" :: "l"(xb + off));
        }
    }

    grid_barrier(&g_b1);

    // ========= Phase 2: v[b,d] += q0[b,e-chunk]·Wk[e-chunk,d] =============
    if (bx < 128) {
        int e0 = (bx >> 1) * 16;
        int d = (bx & 1) * 512 + tid;
        if (tid < BB * 16) {
            int b = tid >> 4, j = tid & 15;
            qs[b][j] = __ldcg(&g_q0[b * DIM + e0 + j]);
        }
        __syncthreads();

        float vacc[BB];
#pragma unroll
        for (int b = 0; b < BB; b++) vacc[b] = 0.0f;
#pragma unroll
        for (int j = 0; j < 16; j++) {
            float w = __ldcs(&Wk[(size_t)(e0 + j) * DIM + d]);
#pragma unroll
            for (int b = 0; b < BB; b++) vacc[b] += qs[b][j] * w;
        }
#pragma unroll
        for (int b = 0; b < BB; b++) atomicAdd(&g_v[b * DIM + d], vacc[b]);
    }

    grid_barrier(&g_b2);

    // ========= Phase 3: TMA double-buffered x stream ======================
    float4* vsm = (float4*)dyn;          // 2048 float4 (32 KB)
    float* xbuf0 = dyn + 8192;           // buffer 0: 16384 floats (64 KB)
    float* xbuf1 = dyn + 8192 + 16384;   // buffer 1
    uint32_t xbs[2] = {smem_u32(xbuf0), smem_u32(xbuf1)};
    float* xbp[2] = {xbuf0, xbuf1};
    uint32_t mbs[2] = {mb0, mb1};

#pragma unroll
    for (int j = 0; j < 4; j++) {
        int idx = tid + 512 * j;
        vsm[idx] = __ldcg((const float4*)g_v + idx);
    }
    __syncthreads();

    uint32_t ph[2] = {0u, 0u};
    int have_prev = 0, prev_buf = 0, it = 0;
    unsigned int prev_r0 = 0;

    for (;;) {
        if (tid == 0) s_r0 = atomicAdd(&g_row, (unsigned)CHUNK);
        __syncthreads();
        unsigned int r0 = s_r0;
        bool valid = (r0 < (unsigned)TOTAL_ROWS);
        int buf = it & 1;
        if (valid && tid == 0) {
            mbar_expect_tx(mbs[buf], CHUNK_BYTES);
            tma_bulk_g2s(xbs[buf], xb + ((size_t)r0 << 12), CHUNK_BYTES,
                         mbs[buf]);
        }
        if (have_prev) {
            mbar_wait(mbs[prev_buf], ph[prev_buf]);
            ph[prev_buf] ^= 1u;
            // 16 warps: one row each, from smem
            int r = (int)prev_r0 + warp;
            int cb = r >> 12;
            const float4* xr4 = (const float4*)xbp[prev_buf] + warp * 256;
            const float4* vv = vsm + cb * 256;
            float a0 = 0.0f, a1 = 0.0f;
#pragma unroll
            for (int j = 0; j < 8; j += 2) {
                float4 u0 = xr4[lane + 32 * j];
                float4 u1 = xr4[lane + 32 * (j + 1)];
                float4 v0 = vv[lane + 32 * j];
                float4 v1 = vv[lane + 32 * (j + 1)];
                a0 += u0.x * v0.x + u0.y * v0.y + u0.z * v0.z + u0.w * v0.w;
                a1 += u1.x * v1.x + u1.y * v1.y + u1.z * v1.z + u1.w * v1.w;
            }
            float acc = warp_sum(a0 + a1);
            if (lane == 0) g_scores[r] = acc;
            __syncthreads();  // all warps done with prev buffer before reuse
        }
        if (!valid) break;
        prev_r0 = r0;
        prev_buf = buf;
        have_prev = 1;
        it++;
    }

    grid_barrier(&g_b3);

    // ========= End-of-run housekeeping (for next replay) ==================
    if (bx >= 8 && bx < 24) {
        g_v[(bx - 8) * 512 + tid] = 0.0f;
    } else if (bx >= 24 && bx < 40) {
        g_q0[(bx - 24) * 512 + tid] = 0.0f;
    } else if (bx == 40 && tid == 0) {
        g_row = 0u;
    }

    // ========= Phase 4: softmax, blocks 0..7 ==============================
    if (bx >= 8) return;
    int sb = bx;

    float s[8];
#pragma unroll
    for (int i = 0; i < 8; i++)
        s[i] = __ldcg(&g_scores[sb * NN + tid + i * 512]);

    float m = s[0];
#pragma unroll
    for (int i = 1; i < 8; i++) m = fmaxf(m, s[i]);
#pragma unroll
    for (int off = 16; off > 0; off >>= 1)
        m = fmaxf(m, __shfl_down_sync(0xFFFFFFFFu, m, off));
    if (lane == 0) red[warp] = m;
    __syncthreads();
    if (warp == 0) {
        float v = (lane < 16) ? red[lane] : -1e30f;
#pragma unroll
        for (int off = 16; off > 0; off >>= 1)
            v = fmaxf(v, __shfl_down_sync(0xFFFFFFFFu, v, off));
        if (lane == 0) bcast = v;
    }
    __syncthreads();
    float M = bcast;

    float e[8];
    float local = 0.0f;
#pragma unroll
    for (int i = 0; i < 8; i++) {
        e[i] = expf(s[i] - M);
        local += e[i];
    }
    local = warp_sum(local);
    if (lane == 0) red[warp] = local;
    __syncthreads();
    if (warp == 0) {
        float v = (lane < 16) ? red[lane] : 0.0f;
        v = warp_sum(v);
        if (lane == 0) bcast = v;
    }
    __syncthreads();
    float inv = 1.0f / bcast;

#pragma unroll
    for (int i = 0; i < 8; i++)
        out[sb * NN + tid + i * 512] = e[i] * inv;
}

extern "C" void kernel_launch(void* const* d_in, const int* in_sizes, int n_in,
                              void* d_out, int out_size) {
    const float* x  = (const float*)d_in[0];
    const float* Wq = (const float*)d_in[1];
    const float* bq = (const float*)d_in[2];
    const float* Wk = (const float*)d_in[3];
    // bk (d_in[4]) is mathematically dead: it shifts every score in a row by
    // the same constant, which cancels in softmax.
    float* out = (float*)d_out;

    cudaFuncSetAttribute(k_fused, cudaFuncAttributeMaxDynamicSharedMemorySize,
                         DSMEM_BYTES);
    k_fused<<<GRID, 512, DSMEM_BYTES>>>(x, Wq, bq, Wk, out);
}

// round 17
// speedup vs baseline: 1.1355x; 1.1355x over previous
#include <cuda_runtime.h>
#include <math.h>

#define BB 8
#define NN 4096
#define DIM 1024
#define GRID 296            // 148 SMs x 2 CTAs, all resident
#define TOTAL_ROWS (BB * NN)
#define CHUNK 32            // rows per dynamic grab
#define PF_ROWS 8064        // x rows L2-prefetched during prepass (31.5 MB)

// Scratch (no allocation allowed). Zero at load; re-zeroed at end of each run.
__device__ float g_v[BB * DIM];
__device__ float g_scores[BB * NN];
__device__ unsigned int g_b1, g_b2;        // monotonic barrier counters
__device__ unsigned int g_row;             // phase-3 ticket (reset at end)

__device__ __forceinline__ float warp_sum(float v) {
#pragma unroll
    for (int off = 16; off > 0; off >>= 1)
        v += __shfl_down_sync(0xFFFFFFFFu, v, off);
    return v;
}

// Monotonic grid barrier: atomic arrival, volatile-load poll.
__device__ __forceinline__ void grid_barrier(unsigned int* ctr) {
    __shared__ unsigned int s_tk;
    __threadfence();
    __syncthreads();
    if (threadIdx.x == 0) s_tk = atomicAdd(ctr, 1u);
    __syncthreads();
    unsigned int target = (s_tk / GRID + 1u) * GRID;
    if (threadIdx.x == 0) {
        volatile unsigned int* vc = (volatile unsigned int*)ctr;
        while (*vc < target) __nanosleep(32);
    }
    __syncthreads();
    __threadfence();
}

// One row-dot: x[r,:] (1024 f32) . v (in smem). LCG: L2-resident path.
template <bool LCG>
__device__ __forceinline__ float row_dot(const float4* __restrict__ xr4,
                                         const float4* __restrict__ vsm,
                                         int lane) {
    float a0 = 0.0f, a1 = 0.0f;
#pragma unroll
    for (int j = 0; j < 8; j += 2) {
        float4 u0 = LCG ? __ldcg(&xr4[lane + 32 * j])
                        : __ldcs(&xr4[lane + 32 * j]);
        float4 u1 = LCG ? __ldcg(&xr4[lane + 32 * (j + 1)])
                        : __ldcs(&xr4[lane + 32 * (j + 1)]);
        float4 v0 = vsm[lane + 32 * j];
        float4 v1 = vsm[lane + 32 * (j + 1)];
        a0 += u0.x * v0.x + u0.y * v0.y + u0.z * v0.z + u0.w * v0.w;
        a1 += u1.x * v1.x + u1.y * v1.y + u1.z * v1.z + u1.w * v1.w;
    }
    return a0 + a1;
}

__global__ void __launch_bounds__(512, 2)
k_fused(const float* __restrict__ x, const float* __restrict__ Wq,
        const float* __restrict__ bq, const float* __restrict__ Wk,
        float* __restrict__ out) {
    __shared__ float4 buf4[BB * DIM / 4];  // 32 KB: x0 stage (ph1) / vs (ph3)
    __shared__ float qs[BB][16];           // per-block q0 chunk (no global q0!)
    __shared__ float red[16];
    __shared__ float bcast;
    __shared__ unsigned int s_r0;

    int tid = threadIdx.x;
    int bx = blockIdx.x;
    int warp = tid >> 5, lane = tid & 31;
    const char* xb = (const char*)x;

    // ========= Merged prepass (blocks 0..63): q0 chunk -> v partial =======
    // Block bx owns e0 = bx*16 .. +15. Computes q0[b, e0+w] per warp into
    // smem, then immediately v[b,d] += sum_j qs[b][j] * Wk[e0+j, d].
    if (bx < 64) {
        // stage x[b,0,:]: 2048 float4 over 512 threads (MLP 4)
#pragma unroll
        for (int j = 0; j < 4; j++) {
            int idx = tid + 512 * j;
            int b = idx >> 8, d4 = idx & 255;
            buf4[idx] = ((const float4*)x)[(size_t)b * (NN * DIM / 4) + d4];
        }
        __syncthreads();

        int e = bx * 16 + warp;            // 0..1023, one full e-row per warp
        const float4* wrow4 = (const float4*)Wq + (size_t)e * 256;
        float acc[BB];
#pragma unroll
        for (int b = 0; b < BB; b++) acc[b] = 0.0f;
#pragma unroll
        for (int j = 0; j < 8; j++) {
            int i = lane + 32 * j;
            float4 w4 = wrow4[i];
#pragma unroll
            for (int b = 0; b < BB; b++) {
                float4 x4 = buf4[b * 256 + i];
                acc[b] += w4.x * x4.x + w4.y * x4.y + w4.z * x4.z + w4.w * x4.w;
            }
        }
#pragma unroll
        for (int b = 0; b < BB; b++) acc[b] = warp_sum(acc[b]);
        if (lane == 0) {
            float bias = bq[e];
#pragma unroll
            for (int b = 0; b < BB; b++) qs[b][warp] = acc[b] + bias;
        }
        __syncthreads();

        // v partial for this e-chunk: each thread covers d = tid, tid+512.
        int e0 = bx * 16;
        float v0[BB], v1[BB];
#pragma unroll
        for (int b = 0; b < BB; b++) { v0[b] = 0.0f; v1[b] = 0.0f; }
#pragma unroll
        for (int j = 0; j < 16; j++) {
            const float* wrow = Wk + (size_t)(e0 + j) * DIM;
            float w0 = __ldcs(&wrow[tid]);
            float w1 = __ldcs(&wrow[tid + 512]);
#pragma unroll
            for (int b = 0; b < BB; b++) {
                float q = qs[b][j];
                v0[b] += q * w0;
                v1[b] += q * w1;
            }
        }
#pragma unroll
        for (int b = 0; b < BB; b++) {
            atomicAdd(&g_v[b * DIM + tid], v0[b]);
            atomicAdd(&g_v[b * DIM + tid + 512], v1[b]);
        }
    } else if (bx < 232) {
        // x prefetch: 168 blocks x 48 rows = 8064 rows = 31.5 MB into L2.
        int pb = bx - 64;                  // 0..167
        int r0 = pb * 48 + warp * 3;
#pragma unroll
        for (int k = 0; k < 3; k++) {
            size_t off = ((size_t)(r0 + k) << 12) + ((size_t)lane << 7);
            asm volatile("prefetch.global.L2 [%0];" :: "l"(xb + off));
        }
    } else {
        // Wq prefetch: 64 blocks x 16 warps = 1024 warps, one 4 KB row each.
        int wrow = (bx - 232) * 16 + warp;
        const char* wqb = (const char*)Wq;
        size_t off = ((size_t)wrow << 12) + ((size_t)lane << 7);
        asm volatile("prefetch.global.L2 [%0];" :: "l"(wqb + off));
    }

    grid_barrier(&g_b1);

    // ========= Phase 3: scores[r] = x[r,:]·v[b(r),:]  (dynamic chunks) ====
#pragma unroll
    for (int j = 0; j < 4; j++) {
        int idx = tid + 512 * j;
        buf4[idx] = __ldcg((const float4*)g_v + idx);
    }
    __syncthreads();

    for (;;) {
        if (tid == 0) s_r0 = atomicAdd(&g_row, (unsigned)CHUNK);
        __syncthreads();
        unsigned int r0 = s_r0;
        if (r0 >= (unsigned)TOTAL_ROWS) break;
        bool inL2 = (r0 < (unsigned)PF_ROWS);  // PF_ROWS is CHUNK-aligned
#pragma unroll
        for (int k = 0; k < 2; k++) {
            int r = (int)r0 + k * 16 + warp;
            int b = r >> 12;
            const float4* xr4 = (const float4*)x + (size_t)r * 256;
            const float4* vsm = buf4 + b * 256;
            float acc = inL2 ? row_dot<true>(xr4, vsm, lane)
                             : row_dot<false>(xr4, vsm, lane);
            acc = warp_sum(acc);
            if (lane == 0) g_scores[r] = acc;
        }
        __syncthreads();
    }

    grid_barrier(&g_b2);

    // ========= End-of-run housekeeping (for next replay) ==================
    if (bx >= 8 && bx < 24) {
        g_v[(bx - 8) * 512 + tid] = 0.0f;
    } else if (bx == 24 && tid == 0) {
        g_row = 0u;
    }

    // ========= Phase 4: softmax, blocks 0..7 ==============================
    if (bx >= 8) return;
    int sb = bx;

    float s[8];
#pragma unroll
    for (int i = 0; i < 8; i++)
        s[i] = __ldcg(&g_scores[sb * NN + tid + i * 512]);

    float m = s[0];
#pragma unroll
    for (int i = 1; i < 8; i++) m = fmaxf(m, s[i]);
#pragma unroll
    for (int off = 16; off > 0; off >>= 1)
        m = fmaxf(m, __shfl_down_sync(0xFFFFFFFFu, m, off));
    if (lane == 0) red[warp] = m;
    __syncthreads();
    if (warp == 0) {
        float v = (lane < 16) ? red[lane] : -1e30f;
#pragma unroll
        for (int off = 16; off > 0; off >>= 1)
            v = fmaxf(v, __shfl_down_sync(0xFFFFFFFFu, v, off));
        if (lane == 0) bcast = v;
    }
    __syncthreads();
    float M = bcast;

    float e[8];
    float local = 0.0f;
#pragma unroll
    for (int i = 0; i < 8; i++) {
        e[i] = expf(s[i] - M);
        local += e[i];
    }
    local = warp_sum(local);
    if (lane == 0) red[warp] = local;
    __syncthreads();
    if (warp == 0) {
        float v = (lane < 16) ? red[lane] : 0.0f;
        v = warp_sum(v);
        if (lane == 0) bcast = v;
    }
    __syncthreads();
    float inv = 1.0f / bcast;

#pragma unroll
    for (int i = 0; i < 8; i++)
        out[sb * NN + tid + i * 512] = e[i] * inv;
}

extern "C" void kernel_launch(void* const* d_in, const int* in_sizes, int n_in,
                              void* d_out, int out_size) {
    const float* x  = (const float*)d_in[0];
    const float* Wq = (const float*)d_in[1];
    const float* bq = (const float*)d_in[2];
    const float* Wk = (const float*)d_in[3];
    // bk (d_in[4]) is mathematically dead: it shifts every score in a row by
    // the same constant, which cancels in softmax.
    float* out = (float*)d_out;

    k_fused<<<GRID, 512>>>(x, Wq, bq, Wk, out);
}